// round 3
// baseline (speedup 1.0000x reference)
#include <cuda_runtime.h>
#include <cstdint>
#include <cstddef>

#define BATCH 16

// ---------------- scratch (no cudaMalloc allowed) ----------------
__device__ __align__(16) float g_h1[2048 * BATCH];
__device__ __align__(16) float g_h2[8192 * BATCH];
__device__ __align__(16) float g_h3[32768 * BATCH];
__device__ __align__(16) float g_h4[131072 * BATCH];
__device__ double g_kl;

// ---------------- JAX threefry2x32 (20 rounds) ----------------
__host__ __device__ __forceinline__ void tf2x32(uint32_t k0, uint32_t k1,
                                                uint32_t x0, uint32_t x1,
                                                uint32_t& y0, uint32_t& y1) {
    uint32_t ks0 = k0, ks1 = k1, ks2 = k0 ^ k1 ^ 0x1BD11BDAu;
    x0 += ks0; x1 += ks1;
#define RND(r) { x0 += x1; x1 = (x1 << (r)) | (x1 >> (32 - (r))); x1 ^= x0; }
    RND(13) RND(15) RND(26) RND(6)   x0 += ks1; x1 += ks2 + 1u;
    RND(17) RND(29) RND(16) RND(24)  x0 += ks2; x1 += ks0 + 2u;
    RND(13) RND(15) RND(26) RND(6)   x0 += ks0; x1 += ks1 + 3u;
    RND(17) RND(29) RND(16) RND(24)  x0 += ks1; x1 += ks2 + 4u;
    RND(13) RND(15) RND(26) RND(6)   x0 += ks2; x1 += ks0 + 5u;
#undef RND
    y0 = x0; y1 = x1;
}

// partitionable threefry random_bits, 32-bit, element i (i < 2^32 so hi=0)
__device__ __forceinline__ uint32_t rbits(uint32_t k0, uint32_t k1, uint32_t i) {
    uint32_t y0, y1;
    tf2x32(k0, k1, 0u, i, y0, y1);
    return y0 ^ y1;
}

// XLA ErfInv32 polynomial (Giles) — matches lax.erf_inv on f32
__device__ __forceinline__ float erfinv_xla(float x) {
    float w = -log1pf(-x * x);
    float p;
    if (w < 5.0f) {
        w -= 2.5f;
        p = 2.81022636e-08f;
        p = fmaf(p, w, 3.43273939e-07f);
        p = fmaf(p, w, -3.5233877e-06f);
        p = fmaf(p, w, -4.39150654e-06f);
        p = fmaf(p, w, 0.00021858087f);
        p = fmaf(p, w, -0.00125372503f);
        p = fmaf(p, w, -0.00417768164f);
        p = fmaf(p, w, 0.246640727f);
        p = fmaf(p, w, 1.50140941f);
    } else {
        w = sqrtf(w) - 3.0f;
        p = -0.000200214257f;
        p = fmaf(p, w, 0.000100950558f);
        p = fmaf(p, w, 0.00134934322f);
        p = fmaf(p, w, -0.00367342844f);
        p = fmaf(p, w, 0.00573950773f);
        p = fmaf(p, w, -0.0076224613f);
        p = fmaf(p, w, 0.00943887047f);
        p = fmaf(p, w, 1.00167406f);
        p = fmaf(p, w, 2.83297682f);
    }
    return p * x;
}

// jax.random.normal: uniform in [nextafter(-1,0), 1) then sqrt(2)*erfinv
__device__ __forceinline__ float bits_to_normal(uint32_t bits) {
    float f = __uint_as_float((bits >> 9) | 0x3f800000u) - 1.0f;  // [0,1)
    const float LO = -0.99999994f;                                 // nextafterf(-1,0)
    float u = fmaxf(LO, fmaf(f, 2.0f, LO));                        // (hi-lo)==2.0f exactly
    return 1.41421356237309515f * erfinv_xla(u);
}

// ---------------- fused stage kernel ----------------
// One thread per fine node f. Computes variational weights (4 edges x C outs),
// gathers/accumulates over 16 batches, then (BN stages) per-node BN + ReLU +
// dropout with node-major store, or (final stage) batch-major [B,N,3] store.
template <int C, bool HASBN, bool X_BATCH_MAJOR>
__global__ __launch_bounds__(256)
void stage_kernel(const float* __restrict__ x,
                  const int* __restrict__ ii,
                  const float* __restrict__ mu,
                  const float* __restrict__ rho,
                  const float* __restrict__ gamma,
                  const float* __restrict__ beta,
                  float* __restrict__ out,
                  int nc, int nf,
                  uint32_t wk0, uint32_t wk1,
                  uint32_t dk0, uint32_t dk1) {
    int f = blockIdx.x * blockDim.x + threadIdx.x;
    float kl = 0.0f;
    if (f < nf) {
        const int4 e4 = *reinterpret_cast<const int4*>(ii + 4 * f);
        const int e[4] = {e4.x, e4.y, e4.z, e4.w};

        // sample variational weights + accumulate KL
        float w[4][C];
#pragma unroll
        for (int j = 0; j < 4; j++) {
#pragma unroll
            for (int o = 0; o < C; o++) {
                uint32_t idx = (uint32_t)((4 * f + j) * C + o);
                float eps = bits_to_normal(rbits(wk0, wk1, idx));
                float m = __ldg(mu + idx);
                float r = __ldg(rho + idx);
                float sp = fmaxf(r, 0.0f) + log1pf(expf(-fabsf(r)));  // softplus
                w[j][o] = fmaf(sp, eps, m);
                kl += 0.5f * (sp * sp + m * m) - logf(sp) - 0.5f;
            }
        }

        float acc[BATCH][C];
#pragma unroll
        for (int b = 0; b < BATCH; b++)
#pragma unroll
            for (int o = 0; o < C; o++) acc[b][o] = 0.0f;

#pragma unroll
        for (int j = 0; j < 4; j++) {
            if (X_BATCH_MAJOR) {
#pragma unroll
                for (int b = 0; b < BATCH; b++) {
                    float xv = __ldg(x + (size_t)b * nc + e[j]);
#pragma unroll
                    for (int o = 0; o < C; o++) acc[b][o] = fmaf(xv, w[j][o], acc[b][o]);
                }
            } else {
                const float4* xp = reinterpret_cast<const float4*>(x + (size_t)e[j] * BATCH);
#pragma unroll
                for (int q = 0; q < 4; q++) {
                    float4 v = __ldg(xp + q);
                    float xv4[4] = {v.x, v.y, v.z, v.w};
#pragma unroll
                    for (int t = 0; t < 4; t++)
#pragma unroll
                        for (int o = 0; o < C; o++)
                            acc[4 * q + t][o] = fmaf(xv4[t], w[j][o], acc[4 * q + t][o]);
                }
            }
        }

        if (HASBN) {  // C == 1 on BN stages
            float s = 0.0f;
#pragma unroll
            for (int b = 0; b < BATCH; b++) s += acc[b][0];
            float m = s * (1.0f / BATCH);
            float vs = 0.0f;
#pragma unroll
            for (int b = 0; b < BATCH; b++) { float d = acc[b][0] - m; vs = fmaf(d, d, vs); }
            vs *= (1.0f / BATCH);
            float inv = rsqrtf(vs + 1e-5f);
            float gg = __ldg(gamma + f), bb = __ldg(beta + f);
            float vals[BATCH];
#pragma unroll
            for (int b = 0; b < BATCH; b++)
                vals[b] = fmaxf((acc[b][0] - m) * inv * gg + bb, 0.0f);
            // dropout: bernoulli(keep=0.9) via exact-bit uniform threshold
#pragma unroll
            for (int b = 0; b < BATCH; b++) {
                uint32_t bits = rbits(dk0, dk1, (uint32_t)(b * nf + f));
                float u = __uint_as_float((bits >> 9) | 0x3f800000u) - 1.0f;
                vals[b] = (u < 0.9f) ? vals[b] / 0.9f : 0.0f;
            }
            float4* op = reinterpret_cast<float4*>(out + (size_t)f * BATCH);
            op[0] = make_float4(vals[0], vals[1], vals[2], vals[3]);
            op[1] = make_float4(vals[4], vals[5], vals[6], vals[7]);
            op[2] = make_float4(vals[8], vals[9], vals[10], vals[11]);
            op[3] = make_float4(vals[12], vals[13], vals[14], vals[15]);
        } else {  // final stage: out layout [B, nf, C]
#pragma unroll
            for (int b = 0; b < BATCH; b++) {
                size_t base = (size_t)b * nf * C + (size_t)f * C;
#pragma unroll
                for (int o = 0; o < C; o++) out[base + o] = acc[b][o];
            }
        }
    }

    // KL block reduction -> double atomic
#pragma unroll
    for (int off = 16; off > 0; off >>= 1)
        kl += __shfl_down_sync(0xffffffffu, kl, off);
    __shared__ float wsum[8];
    int lane = threadIdx.x & 31, wid = threadIdx.x >> 5;
    if (lane == 0) wsum[wid] = kl;
    __syncthreads();
    if (threadIdx.x == 0) {
        double s = 0.0;
        int nw = (blockDim.x + 31) >> 5;
        for (int i = 0; i < nw; i++) s += (double)wsum[i];
        atomicAdd(&g_kl, s);
    }
}

__global__ void zero_kl_kernel() { g_kl = 0.0; }
__global__ void write_kl_kernel(float* out, size_t idx) { out[idx] = (float)g_kl; }

// ---------------- launch ----------------
extern "C" void kernel_launch(void* const* d_in, const int* in_sizes, int n_in,
                              void* d_out, int out_size) {
    (void)in_sizes; (void)n_in;
    const float* x = (const float*)d_in[0];
    const int*   ii[5]  = {(const int*)d_in[2],  (const int*)d_in[8],  (const int*)d_in[14],
                           (const int*)d_in[20], (const int*)d_in[26]};
    const float* mu[5]  = {(const float*)d_in[3],  (const float*)d_in[9],  (const float*)d_in[15],
                           (const float*)d_in[21], (const float*)d_in[27]};
    const float* rho[5] = {(const float*)d_in[4],  (const float*)d_in[10], (const float*)d_in[16],
                           (const float*)d_in[22], (const float*)d_in[28]};
    const float* gam[4] = {(const float*)d_in[5],  (const float*)d_in[11],
                           (const float*)d_in[17], (const float*)d_in[23]};
    const float* bet[4] = {(const float*)d_in[6],  (const float*)d_in[12],
                           (const float*)d_in[18], (const float*)d_in[24]};

    // keys = split(key(42), 10), partitionable fold-like: keys[m] = tf((0,42), 0, m)
    uint32_t k[10][2];
    for (uint32_t m = 0; m < 10; m++) tf2x32(0u, 42u, 0u, m, k[m][0], k[m][1]);

    float *h1, *h2, *h3, *h4;
    cudaGetSymbolAddress((void**)&h1, g_h1);
    cudaGetSymbolAddress((void**)&h2, g_h2);
    cudaGetSymbolAddress((void**)&h3, g_h3);
    cudaGetSymbolAddress((void**)&h4, g_h4);

    zero_kl_kernel<<<1, 1>>>();

    stage_kernel<1, true, true><<<2048 / 256, 256>>>(
        x, ii[0], mu[0], rho[0], gam[0], bet[0], h1, 512, 2048,
        k[0][0], k[0][1], k[1][0], k[1][1]);
    stage_kernel<1, true, false><<<8192 / 256, 256>>>(
        h1, ii[1], mu[1], rho[1], gam[1], bet[1], h2, 2048, 8192,
        k[2][0], k[2][1], k[3][0], k[3][1]);
    stage_kernel<1, true, false><<<32768 / 256, 256>>>(
        h2, ii[2], mu[2], rho[2], gam[2], bet[2], h3, 8192, 32768,
        k[4][0], k[4][1], k[5][0], k[5][1]);
    stage_kernel<1, true, false><<<131072 / 256, 256>>>(
        h3, ii[3], mu[3], rho[3], gam[3], bet[3], h4, 32768, 131072,
        k[6][0], k[6][1], k[7][0], k[7][1]);
    stage_kernel<3, false, false><<<524288 / 256, 256>>>(
        h4, ii[4], mu[4], rho[4], nullptr, nullptr, (float*)d_out, 131072, 524288,
        k[8][0], k[8][1], 0u, 0u);

    write_kl_kernel<<<1, 1>>>((float*)d_out, (size_t)out_size - 1);
}

// round 4
// speedup vs baseline: 1.3612x; 1.3612x over previous
#include <cuda_runtime.h>
#include <cstdint>
#include <cstddef>

#define BATCH 16

// ---------------- scratch (no cudaMalloc allowed) ----------------
__device__ __align__(16) float g_h1[2048 * BATCH];
__device__ __align__(16) float g_h2[8192 * BATCH];
__device__ __align__(16) float g_h3[32768 * BATCH];
__device__ __align__(16) float g_h4[131072 * BATCH];
__device__ double g_kl;

// ---------------- JAX threefry2x32 (20 rounds) ----------------
__host__ __device__ __forceinline__ void tf2x32(uint32_t k0, uint32_t k1,
                                                uint32_t x0, uint32_t x1,
                                                uint32_t& y0, uint32_t& y1) {
    uint32_t ks0 = k0, ks1 = k1, ks2 = k0 ^ k1 ^ 0x1BD11BDAu;
    x0 += ks0; x1 += ks1;
#define RND(r) { x0 += x1; x1 = (x1 << (r)) | (x1 >> (32 - (r))); x1 ^= x0; }
    RND(13) RND(15) RND(26) RND(6)   x0 += ks1; x1 += ks2 + 1u;
    RND(17) RND(29) RND(16) RND(24)  x0 += ks2; x1 += ks0 + 2u;
    RND(13) RND(15) RND(26) RND(6)   x0 += ks0; x1 += ks1 + 3u;
    RND(17) RND(29) RND(16) RND(24)  x0 += ks1; x1 += ks2 + 4u;
    RND(13) RND(15) RND(26) RND(6)   x0 += ks2; x1 += ks0 + 5u;
#undef RND
    y0 = x0; y1 = x1;
}

// partitionable threefry random_bits, 32-bit, element i (i < 2^32 so hi=0)
__device__ __forceinline__ uint32_t rbits(uint32_t k0, uint32_t k1, uint32_t i) {
    uint32_t y0, y1;
    tf2x32(k0, k1, 0u, i, y0, y1);
    return y0 ^ y1;
}

// XLA ErfInv32 polynomial (Giles) — matches lax.erf_inv on f32
__device__ __forceinline__ float erfinv_xla(float x) {
    float w = -log1pf(-x * x);
    float p;
    if (w < 5.0f) {
        w -= 2.5f;
        p = 2.81022636e-08f;
        p = fmaf(p, w, 3.43273939e-07f);
        p = fmaf(p, w, -3.5233877e-06f);
        p = fmaf(p, w, -4.39150654e-06f);
        p = fmaf(p, w, 0.00021858087f);
        p = fmaf(p, w, -0.00125372503f);
        p = fmaf(p, w, -0.00417768164f);
        p = fmaf(p, w, 0.246640727f);
        p = fmaf(p, w, 1.50140941f);
    } else {
        w = sqrtf(w) - 3.0f;
        p = -0.000200214257f;
        p = fmaf(p, w, 0.000100950558f);
        p = fmaf(p, w, 0.00134934322f);
        p = fmaf(p, w, -0.00367342844f);
        p = fmaf(p, w, 0.00573950773f);
        p = fmaf(p, w, -0.0076224613f);
        p = fmaf(p, w, 0.00943887047f);
        p = fmaf(p, w, 1.00167406f);
        p = fmaf(p, w, 2.83297682f);
    }
    return p * x;
}

// jax.random.normal: uniform in [nextafter(-1,0), 1) then sqrt(2)*erfinv
__device__ __forceinline__ float bits_to_normal(uint32_t bits) {
    float f = __uint_as_float((bits >> 9) | 0x3f800000u) - 1.0f;  // [0,1)
    const float LO = -0.99999994f;                                 // nextafterf(-1,0)
    float u = fmaxf(LO, fmaf(f, 2.0f, LO));                        // (hi-lo)==2.0f exactly
    return 1.41421356237309515f * erfinv_xla(u);
}

// ---------------- quad-split fused stage kernel ----------------
// 4 threads per fine node f (sub = tid&3). Thread `sub` samples the weight(s)
// of edge `sub`, shares all 4 edges' weights via quad shuffles, accumulates
// batches [4*sub, 4*sub+4), then BN (quad shfl_xor stats) + ReLU + dropout
// (node-major float4 store) or final [B,N,3] store.
template <int C, bool HASBN, bool X_BATCH_MAJOR>
__global__ __launch_bounds__(256)
void stage_kernel(const float* __restrict__ x,
                  const int* __restrict__ ii,
                  const float* __restrict__ mu,
                  const float* __restrict__ rho,
                  const float* __restrict__ gamma,
                  const float* __restrict__ beta,
                  float* __restrict__ out,
                  int nc, int nf,
                  uint32_t wk0, uint32_t wk1,
                  uint32_t dk0, uint32_t dk1) {
    const int tid = blockIdx.x * blockDim.x + threadIdx.x;
    const int f = tid >> 2;
    const int sub = tid & 3;
    const int lane = threadIdx.x & 31;
    const int qbase = lane & ~3;

    float kl = 0.0f;
    // grids are sized exactly (nf*4 multiple of 256) so every thread is live
    {
        const int4 e4 = __ldg(reinterpret_cast<const int4*>(ii) + f);  // quad broadcast
        const int e[4] = {e4.x, e4.y, e4.z, e4.w};

        // --- own edge's weight(s) + KL partial ---
        float w_own[C];
#pragma unroll
        for (int o = 0; o < C; o++) {
            uint32_t idx = (uint32_t)((4 * f + sub) * C + o);
            float eps = bits_to_normal(rbits(wk0, wk1, idx));
            float m = __ldg(mu + idx);
            float r = __ldg(rho + idx);
            float sp = fmaxf(r, 0.0f) + log1pf(expf(-fabsf(r)));  // softplus
            w_own[o] = fmaf(sp, eps, m);
            kl += 0.5f * (sp * sp + m * m) - logf(sp) - 0.5f;
        }

        // --- broadcast all 4 edges' weights within the quad ---
        float w[4][C];
#pragma unroll
        for (int j = 0; j < 4; j++)
#pragma unroll
            for (int o = 0; o < C; o++)
                w[j][o] = __shfl_sync(0xffffffffu, w_own[o], qbase + j);

        // --- gather + accumulate: this thread owns batches 4*sub .. 4*sub+3 ---
        float acc[4][C];
#pragma unroll
        for (int t = 0; t < 4; t++)
#pragma unroll
            for (int o = 0; o < C; o++) acc[t][o] = 0.0f;

#pragma unroll
        for (int j = 0; j < 4; j++) {
            float xv[4];
            if (X_BATCH_MAJOR) {
#pragma unroll
                for (int t = 0; t < 4; t++)
                    xv[t] = __ldg(x + (size_t)(4 * sub + t) * nc + e[j]);
            } else {
                float4 v = __ldg(reinterpret_cast<const float4*>(x + (size_t)e[j] * BATCH) + sub);
                xv[0] = v.x; xv[1] = v.y; xv[2] = v.z; xv[3] = v.w;
            }
#pragma unroll
            for (int t = 0; t < 4; t++)
#pragma unroll
                for (int o = 0; o < C; o++)
                    acc[t][o] = fmaf(xv[t], w[j][o], acc[t][o]);
        }

        if (HASBN) {  // C == 1 on BN stages
            float s = acc[0][0] + acc[1][0] + acc[2][0] + acc[3][0];
            s += __shfl_xor_sync(0xffffffffu, s, 1);
            s += __shfl_xor_sync(0xffffffffu, s, 2);
            float m = s * (1.0f / BATCH);
            float d2 = 0.0f;
#pragma unroll
            for (int t = 0; t < 4; t++) { float d = acc[t][0] - m; d2 = fmaf(d, d, d2); }
            d2 += __shfl_xor_sync(0xffffffffu, d2, 1);
            d2 += __shfl_xor_sync(0xffffffffu, d2, 2);
            float inv = rsqrtf(d2 * (1.0f / BATCH) + 1e-5f);
            float gg = __ldg(gamma + f), bb = __ldg(beta + f);
            float vals[4];
#pragma unroll
            for (int t = 0; t < 4; t++)
                vals[t] = fmaxf((acc[t][0] - m) * inv * gg + bb, 0.0f);
            // dropout: bernoulli(keep=0.9), exact-bit uniform threshold
#pragma unroll
            for (int t = 0; t < 4; t++) {
                uint32_t bits = rbits(dk0, dk1, (uint32_t)((4 * sub + t) * nf + f));
                float u = __uint_as_float((bits >> 9) | 0x3f800000u) - 1.0f;
                vals[t] = (u < 0.9f) ? vals[t] / 0.9f : 0.0f;
            }
            reinterpret_cast<float4*>(out + (size_t)f * BATCH)[sub] =
                make_float4(vals[0], vals[1], vals[2], vals[3]);
        } else {  // final stage: out layout [B, nf, C]
#pragma unroll
            for (int t = 0; t < 4; t++) {
                size_t base = (size_t)(4 * sub + t) * nf * C + (size_t)f * C;
#pragma unroll
                for (int o = 0; o < C; o++) out[base + o] = acc[t][o];
            }
        }
    }

    // KL block reduction -> double atomic
#pragma unroll
    for (int off = 16; off > 0; off >>= 1)
        kl += __shfl_down_sync(0xffffffffu, kl, off);
    __shared__ float wsum[8];
    int wid = threadIdx.x >> 5;
    if (lane == 0) wsum[wid] = kl;
    __syncthreads();
    if (threadIdx.x == 0) {
        double s = 0.0;
        int nw = (blockDim.x + 31) >> 5;
        for (int i = 0; i < nw; i++) s += (double)wsum[i];
        atomicAdd(&g_kl, s);
    }
}

__global__ void zero_kl_kernel() { g_kl = 0.0; }
__global__ void write_kl_kernel(float* out, size_t idx) { out[idx] = (float)g_kl; }

// ---------------- launch ----------------
extern "C" void kernel_launch(void* const* d_in, const int* in_sizes, int n_in,
                              void* d_out, int out_size) {
    (void)in_sizes; (void)n_in;
    const float* x = (const float*)d_in[0];
    const int*   ii[5]  = {(const int*)d_in[2],  (const int*)d_in[8],  (const int*)d_in[14],
                           (const int*)d_in[20], (const int*)d_in[26]};
    const float* mu[5]  = {(const float*)d_in[3],  (const float*)d_in[9],  (const float*)d_in[15],
                           (const float*)d_in[21], (const float*)d_in[27]};
    const float* rho[5] = {(const float*)d_in[4],  (const float*)d_in[10], (const float*)d_in[16],
                           (const float*)d_in[22], (const float*)d_in[28]};
    const float* gam[4] = {(const float*)d_in[5],  (const float*)d_in[11],
                           (const float*)d_in[17], (const float*)d_in[23]};
    const float* bet[4] = {(const float*)d_in[6],  (const float*)d_in[12],
                           (const float*)d_in[18], (const float*)d_in[24]};

    // keys = split(key(42), 10), partitionable fold-like: keys[m] = tf((0,42), 0, m)
    uint32_t k[10][2];
    for (uint32_t m = 0; m < 10; m++) tf2x32(0u, 42u, 0u, m, k[m][0], k[m][1]);

    float *h1, *h2, *h3, *h4;
    cudaGetSymbolAddress((void**)&h1, g_h1);
    cudaGetSymbolAddress((void**)&h2, g_h2);
    cudaGetSymbolAddress((void**)&h3, g_h3);
    cudaGetSymbolAddress((void**)&h4, g_h4);

    zero_kl_kernel<<<1, 1>>>();

    // grid = nf*4 threads / 256
    stage_kernel<1, true, true><<<2048 * 4 / 256, 256>>>(
        x, ii[0], mu[0], rho[0], gam[0], bet[0], h1, 512, 2048,
        k[0][0], k[0][1], k[1][0], k[1][1]);
    stage_kernel<1, true, false><<<8192 * 4 / 256, 256>>>(
        h1, ii[1], mu[1], rho[1], gam[1], bet[1], h2, 2048, 8192,
        k[2][0], k[2][1], k[3][0], k[3][1]);
    stage_kernel<1, true, false><<<32768 * 4 / 256, 256>>>(
        h2, ii[2], mu[2], rho[2], gam[2], bet[2], h3, 8192, 32768,
        k[4][0], k[4][1], k[5][0], k[5][1]);
    stage_kernel<1, true, false><<<131072 * 4 / 256, 256>>>(
        h3, ii[3], mu[3], rho[3], gam[3], bet[3], h4, 32768, 131072,
        k[6][0], k[6][1], k[7][0], k[7][1]);
    stage_kernel<3, false, false><<<524288 * 4 / 256, 256>>>(
        h4, ii[4], mu[4], rho[4], nullptr, nullptr, (float*)d_out, 131072, 524288,
        k[8][0], k[8][1], 0u, 0u);

    write_kl_kernel<<<1, 1>>>((float*)d_out, (size_t)out_size - 1);
}

// round 6
// speedup vs baseline: 1.5610x; 1.1467x over previous
#include <cuda_runtime.h>
#include <cstdint>
#include <cstddef>

#define BATCH 16

// ---------------- scratch (no cudaMalloc allowed) ----------------
__device__ __align__(16) float g_h1[2048 * BATCH];
__device__ __align__(16) float g_h2[8192 * BATCH];
__device__ __align__(16) float g_h3[32768 * BATCH];
__device__ __align__(16) float g_h4[131072 * BATCH];
__device__ double g_kl;

// ---------------- JAX threefry2x32 (20 rounds) ----------------
__host__ __device__ __forceinline__ uint32_t rotl(uint32_t v, int r) {
#ifdef __CUDA_ARCH__
    return __funnelshift_l(v, v, r);   // guaranteed single SHF
#else
    return (v << r) | (v >> (32 - r));
#endif
}

__host__ __device__ __forceinline__ void tf2x32(uint32_t k0, uint32_t k1,
                                                uint32_t x0, uint32_t x1,
                                                uint32_t& y0, uint32_t& y1) {
    uint32_t ks0 = k0, ks1 = k1, ks2 = k0 ^ k1 ^ 0x1BD11BDAu;
    x0 += ks0; x1 += ks1;
#define RND(r) { x0 += x1; x1 = rotl(x1, r); x1 ^= x0; }
    RND(13) RND(15) RND(26) RND(6)   x0 += ks1; x1 += ks2 + 1u;
    RND(17) RND(29) RND(16) RND(24)  x0 += ks2; x1 += ks0 + 2u;
    RND(13) RND(15) RND(26) RND(6)   x0 += ks0; x1 += ks1 + 3u;
    RND(17) RND(29) RND(16) RND(24)  x0 += ks1; x1 += ks2 + 4u;
    RND(13) RND(15) RND(26) RND(6)   x0 += ks2; x1 += ks0 + 5u;
#undef RND
    y0 = x0; y1 = x1;
}

// partitionable threefry random_bits, 32-bit, element i (i < 2^32 so hi=0)
__device__ __forceinline__ uint32_t rbits(uint32_t k0, uint32_t k1, uint32_t i) {
    uint32_t y0, y1;
    tf2x32(k0, k1, 0u, i, y0, y1);
    return y0 ^ y1;
}

// XLA ErfInv32 polynomial (Giles), fast-log variant. eps path is continuous,
// so ~1e-6 rel perturbation vs log1pf is fine (only dropout bits must be exact).
__device__ __forceinline__ float erfinv_fast(float x) {
    float w = -__logf(fmaf(-x, x, 1.0f));   // 1-x^2 >= 1.19e-7 always
    float p;
    if (w < 5.0f) {
        w -= 2.5f;
        p = 2.81022636e-08f;
        p = fmaf(p, w, 3.43273939e-07f);
        p = fmaf(p, w, -3.5233877e-06f);
        p = fmaf(p, w, -4.39150654e-06f);
        p = fmaf(p, w, 0.00021858087f);
        p = fmaf(p, w, -0.00125372503f);
        p = fmaf(p, w, -0.00417768164f);
        p = fmaf(p, w, 0.246640727f);
        p = fmaf(p, w, 1.50140941f);
    } else {
        w = sqrtf(w) - 3.0f;
        p = -0.000200214257f;
        p = fmaf(p, w, 0.000100950558f);
        p = fmaf(p, w, 0.00134934322f);
        p = fmaf(p, w, -0.00367342844f);
        p = fmaf(p, w, 0.00573950773f);
        p = fmaf(p, w, -0.0076224613f);
        p = fmaf(p, w, 0.00943887047f);
        p = fmaf(p, w, 1.00167406f);
        p = fmaf(p, w, 2.83297682f);
    }
    return p * x;
}

// jax.random.normal: uniform in [nextafter(-1,0), 1) then sqrt(2)*erfinv
__device__ __forceinline__ float bits_to_normal(uint32_t bits) {
    float f = __uint_as_float((bits >> 9) | 0x3f800000u) - 1.0f;  // [0,1)
    const float LO = -0.99999994f;                                 // nextafterf(-1,0)
    float u = fmaxf(LO, fmaf(f, 2.0f, LO));                        // (hi-lo)==2.0f exactly
    return 1.41421356237309515f * erfinv_fast(u);
}

// ---------------- split fused stage kernel ----------------
// SPLIT threads per fine node f (sub = tid % SPLIT, SPLIT in {4,8}).
// Lanes sub<4 of each group sample edge `sub`'s weight(s); all lanes get all
// 4 edges' weights via group shuffles. Each thread owns TB=16/SPLIT batches.
// BN stats via group shfl_xor; dropout bits exact; vectorized node-major store.
template <int C, int SPLIT, bool HASBN, bool X_BATCH_MAJOR>
__global__ __launch_bounds__(256)
void stage_kernel(const float* __restrict__ x,
                  const int* __restrict__ ii,
                  const float* __restrict__ mu,
                  const float* __restrict__ rho,
                  const float* __restrict__ gamma,
                  const float* __restrict__ beta,
                  float* __restrict__ out,
                  int nc, int nf,
                  uint32_t wk0, uint32_t wk1,
                  uint32_t dk0, uint32_t dk1) {
    constexpr int TB = BATCH / SPLIT;      // batches per thread
    const int tid = blockIdx.x * blockDim.x + threadIdx.x;
    const int f = tid / SPLIT;
    const int sub = tid % SPLIT;
    const int lane = threadIdx.x & 31;
    const int gbase = lane & ~(SPLIT - 1);
    const int b0 = sub * TB;

    float kl = 0.0f;
    {
        const int4 e4 = __ldg(reinterpret_cast<const int4*>(ii) + f);  // group broadcast
        const int e[4] = {e4.x, e4.y, e4.z, e4.w};

        // --- edge weights: lanes sub<4 compute edge `sub` ---
        float w_own[C];
#pragma unroll
        for (int o = 0; o < C; o++) w_own[o] = 0.0f;
        if (SPLIT == 4 || sub < 4) {
#pragma unroll
            for (int o = 0; o < C; o++) {
                uint32_t idx = (uint32_t)((4 * f + sub) * C + o);
                float eps = bits_to_normal(rbits(wk0, wk1, idx));
                float m = __ldg(mu + idx);
                float r = __ldg(rho + idx);
                float t = __expf(-fabsf(r));
                float sp = fmaxf(r, 0.0f) + __logf(1.0f + t);   // softplus
                w_own[o] = fmaf(sp, eps, m);
                kl += 0.5f * (sp * sp + m * m) - __logf(sp) - 0.5f;
            }
        }

        // --- broadcast all 4 edges' weights within the group ---
        float w[4][C];
#pragma unroll
        for (int j = 0; j < 4; j++)
#pragma unroll
            for (int o = 0; o < C; o++)
                w[j][o] = __shfl_sync(0xffffffffu, w_own[o], gbase + j);

        // --- gather + accumulate TB batches ---
        float acc[TB][C];
#pragma unroll
        for (int t = 0; t < TB; t++)
#pragma unroll
            for (int o = 0; o < C; o++) acc[t][o] = 0.0f;

#pragma unroll
        for (int j = 0; j < 4; j++) {
            float xv[TB];
            if (X_BATCH_MAJOR) {
#pragma unroll
                for (int t = 0; t < TB; t++)
                    xv[t] = __ldg(x + (size_t)(b0 + t) * nc + e[j]);
            } else if (TB == 4) {
                float4 v = __ldg(reinterpret_cast<const float4*>(x + (size_t)e[j] * BATCH) + sub);
                xv[0] = v.x; xv[1] = v.y; xv[2] = v.z; xv[3] = v.w;
            } else {  // TB == 2
                float2 v = __ldg(reinterpret_cast<const float2*>(x + (size_t)e[j] * BATCH) + sub);
                xv[0] = v.x; xv[1] = v.y;
            }
#pragma unroll
            for (int t = 0; t < TB; t++)
#pragma unroll
                for (int o = 0; o < C; o++)
                    acc[t][o] = fmaf(xv[t], w[j][o], acc[t][o]);
        }

        if (HASBN) {  // C == 1 on BN stages
            float s = 0.0f;
#pragma unroll
            for (int t = 0; t < TB; t++) s += acc[t][0];
#pragma unroll
            for (int off = 1; off < SPLIT; off <<= 1)
                s += __shfl_xor_sync(0xffffffffu, s, off);
            float m = s * (1.0f / BATCH);
            float d2 = 0.0f;
#pragma unroll
            for (int t = 0; t < TB; t++) { float d = acc[t][0] - m; d2 = fmaf(d, d, d2); }
#pragma unroll
            for (int off = 1; off < SPLIT; off <<= 1)
                d2 += __shfl_xor_sync(0xffffffffu, d2, off);
            float inv = rsqrtf(d2 * (1.0f / BATCH) + 1e-5f);
            float gg = __ldg(gamma + f), bb = __ldg(beta + f);
            float vals[TB];
#pragma unroll
            for (int t = 0; t < TB; t++)
                vals[t] = fmaxf((acc[t][0] - m) * inv * gg + bb, 0.0f);
            // dropout: bernoulli(keep=0.9), exact-bit uniform threshold
#pragma unroll
            for (int t = 0; t < TB; t++) {
                uint32_t bits = rbits(dk0, dk1, (uint32_t)((b0 + t) * nf + f));
                float u = __uint_as_float((bits >> 9) | 0x3f800000u) - 1.0f;
                vals[t] = (u < 0.9f) ? vals[t] / 0.9f : 0.0f;
            }
            if (TB == 4) {
                reinterpret_cast<float4*>(out + (size_t)f * BATCH)[sub] =
                    make_float4(vals[0], vals[1], vals[2], vals[3]);
            } else {
                reinterpret_cast<float2*>(out + (size_t)f * BATCH)[sub] =
                    make_float2(vals[0], vals[1]);
            }
        } else {  // final stage: out layout [B, nf, C]
#pragma unroll
            for (int t = 0; t < TB; t++) {
                size_t base = (size_t)(b0 + t) * nf * C + (size_t)f * C;
#pragma unroll
                for (int o = 0; o < C; o++) out[base + o] = acc[t][o];
            }
        }
    }

    // KL block reduction -> double atomic
#pragma unroll
    for (int off = 16; off > 0; off >>= 1)
        kl += __shfl_down_sync(0xffffffffu, kl, off);
    __shared__ float wsum[8];
    int wid = threadIdx.x >> 5;
    if (lane == 0) wsum[wid] = kl;
    __syncthreads();
    if (threadIdx.x == 0) {
        double s = 0.0;
        int nw = (blockDim.x + 31) >> 5;
        for (int i = 0; i < nw; i++) s += (double)wsum[i];
        atomicAdd(&g_kl, s);
    }
}

__global__ void zero_kl_kernel() { g_kl = 0.0; }
__global__ void write_kl_kernel(float* out, size_t idx) { out[idx] = (float)g_kl; }

// ---------------- launch ----------------
extern "C" void kernel_launch(void* const* d_in, const int* in_sizes, int n_in,
                              void* d_out, int out_size) {
    (void)in_sizes; (void)n_in;
    const float* x = (const float*)d_in[0];
    const int*   ii[5]  = {(const int*)d_in[2],  (const int*)d_in[8],  (const int*)d_in[14],
                           (const int*)d_in[20], (const int*)d_in[26]};
    const float* mu[5]  = {(const float*)d_in[3],  (const float*)d_in[9],  (const float*)d_in[15],
                           (const float*)d_in[21], (const float*)d_in[27]};
    const float* rho[5] = {(const float*)d_in[4],  (const float*)d_in[10], (const float*)d_in[16],
                           (const float*)d_in[22], (const float*)d_in[28]};
    const float* gam[4] = {(const float*)d_in[5],  (const float*)d_in[11],
                           (const float*)d_in[17], (const float*)d_in[23]};
    const float* bet[4] = {(const float*)d_in[6],  (const float*)d_in[12],
                           (const float*)d_in[18], (const float*)d_in[24]};

    // keys = split(key(42), 10), partitionable fold-like: keys[m] = tf((0,42), 0, m)
    uint32_t k[10][2];
    for (uint32_t m = 0; m < 10; m++) tf2x32(0u, 42u, 0u, m, k[m][0], k[m][1]);

    float *h1, *h2, *h3, *h4;
    cudaGetSymbolAddress((void**)&h1, g_h1);
    cudaGetSymbolAddress((void**)&h2, g_h2);
    cudaGetSymbolAddress((void**)&h3, g_h3);
    cudaGetSymbolAddress((void**)&h4, g_h4);

    zero_kl_kernel<<<1, 1>>>();

    // grid = nf*SPLIT threads / 256
    stage_kernel<1, 8, true, true><<<2048 * 8 / 256, 256>>>(
        x, ii[0], mu[0], rho[0], gam[0], bet[0], h1, 512, 2048,
        k[0][0], k[0][1], k[1][0], k[1][1]);
    stage_kernel<1, 8, true, false><<<8192 * 8 / 256, 256>>>(
        h1, ii[1], mu[1], rho[1], gam[1], bet[1], h2, 2048, 8192,
        k[2][0], k[2][1], k[3][0], k[3][1]);
    stage_kernel<1, 8, true, false><<<32768 * 8 / 256, 256>>>(
        h2, ii[2], mu[2], rho[2], gam[2], bet[2], h3, 8192, 32768,
        k[4][0], k[4][1], k[5][0], k[5][1]);
    stage_kernel<1, 4, true, false><<<131072 * 4 / 256, 256>>>(
        h3, ii[3], mu[3], rho[3], gam[3], bet[3], h4, 32768, 131072,
        k[6][0], k[6][1], k[7][0], k[7][1]);
    stage_kernel<3, 4, false, false><<<524288 * 4 / 256, 256>>>(
        h4, ii[4], mu[4], rho[4], nullptr, nullptr, (float*)d_out, 131072, 524288,
        k[8][0], k[8][1], 0u, 0u);

    write_kl_kernel<<<1, 1>>>((float*)d_out, (size_t)out_size - 1);
}

// round 10
// speedup vs baseline: 1.7770x; 1.1384x over previous
#include <cuda_runtime.h>
#include <cstdint>
#include <cstddef>

#define BATCH 16

// ---------------- scratch (no cudaMalloc allowed) ----------------
__device__ __align__(16) float g_h1[2048 * BATCH];
__device__ __align__(16) float g_h2[8192 * BATCH];
__device__ __align__(16) float g_h3[32768 * BATCH];
__device__ __align__(16) float g_h4[131072 * BATCH];
__device__ double g_kl;

// ---------------- JAX threefry2x32 (20 rounds) ----------------
__host__ __device__ __forceinline__ uint32_t rotl(uint32_t v, int r) {
#ifdef __CUDA_ARCH__
    return __funnelshift_l(v, v, r);   // single SHF
#else
    return (v << r) | (v >> (32 - r));
#endif
}

__host__ __device__ __forceinline__ void tf2x32(uint32_t k0, uint32_t k1,
                                                uint32_t x0, uint32_t x1,
                                                uint32_t& y0, uint32_t& y1) {
    uint32_t ks0 = k0, ks1 = k1, ks2 = k0 ^ k1 ^ 0x1BD11BDAu;
    x0 += ks0; x1 += ks1;
#define RND(r) { x0 += x1; x1 = rotl(x1, r); x1 ^= x0; }
    RND(13) RND(15) RND(26) RND(6)   x0 += ks1; x1 += ks2 + 1u;
    RND(17) RND(29) RND(16) RND(24)  x0 += ks2; x1 += ks0 + 2u;
    RND(13) RND(15) RND(26) RND(6)   x0 += ks0; x1 += ks1 + 3u;
    RND(17) RND(29) RND(16) RND(24)  x0 += ks1; x1 += ks2 + 4u;
    RND(13) RND(15) RND(26) RND(6)   x0 += ks2; x1 += ks0 + 5u;
#undef RND
    y0 = x0; y1 = x1;
}

// partitionable threefry random_bits, 32-bit, element i (i < 2^32 so hi=0)
__device__ __forceinline__ uint32_t rbits(uint32_t k0, uint32_t k1, uint32_t i) {
    uint32_t y0, y1;
    tf2x32(k0, k1, 0u, i, y0, y1);
    return y0 ^ y1;
}

// XLA ErfInv32 polynomial (Giles), fast-log variant (eps path is continuous;
// ~1e-6 rel perturbation is fine — only dropout bits must be exact).
__device__ __forceinline__ float erfinv_fast(float x) {
    float w = -__logf(fmaf(-x, x, 1.0f));   // 1-x^2 >= 1.19e-7 always
    float p;
    if (w < 5.0f) {
        w -= 2.5f;
        p = 2.81022636e-08f;
        p = fmaf(p, w, 3.43273939e-07f);
        p = fmaf(p, w, -3.5233877e-06f);
        p = fmaf(p, w, -4.39150654e-06f);
        p = fmaf(p, w, 0.00021858087f);
        p = fmaf(p, w, -0.00125372503f);
        p = fmaf(p, w, -0.00417768164f);
        p = fmaf(p, w, 0.246640727f);
        p = fmaf(p, w, 1.50140941f);
    } else {
        w = sqrtf(w) - 3.0f;
        p = -0.000200214257f;
        p = fmaf(p, w, 0.000100950558f);
        p = fmaf(p, w, 0.00134934322f);
        p = fmaf(p, w, -0.00367342844f);
        p = fmaf(p, w, 0.00573950773f);
        p = fmaf(p, w, -0.0076224613f);
        p = fmaf(p, w, 0.00943887047f);
        p = fmaf(p, w, 1.00167406f);
        p = fmaf(p, w, 2.83297682f);
    }
    return p * x;
}

// jax.random.normal: uniform in [nextafter(-1,0), 1) then sqrt(2)*erfinv
__device__ __forceinline__ float bits_to_normal(uint32_t bits) {
    float f = __uint_as_float((bits >> 9) | 0x3f800000u) - 1.0f;  // [0,1)
    const float LO = -0.99999994f;                                 // nextafterf(-1,0)
    float u = fmaxf(LO, fmaf(f, 2.0f, LO));                        // (hi-lo)==2.0f exactly
    return 1.41421356237309515f * erfinv_fast(u);
}

// dropout keep test in integer space: u < 0.9f  <=>  bits < 0xE6666600
// (0.9f == 7549747*2^-23 exactly; u == (bits>>9)*2^-23 exactly)
#define DROP_KEEP_THRESH 0xE6666600u
#define INV_KEEP 1.11111116409301757813f   // 1.0f/0.9f rounded (<=1 ulp vs div)

// ---------------- split fused stage kernel ----------------
// SPLIT threads per fine node f (sub = tid % SPLIT, SPLIT in {4,8}).
// Scheduling: ALL memory loads issued first, then ALL RNG chains (weight eps +
// dropout bits, independent), then transforms/FMA/BN/store — so L2/DRAM latency
// hides under ~300 instrs of integer RNG.
template <int C, int SPLIT, bool HASBN, bool X_BATCH_MAJOR>
__global__ __launch_bounds__(256)
void stage_kernel(const float* __restrict__ x,
                  const int* __restrict__ ii,
                  const float* __restrict__ mu,
                  const float* __restrict__ rho,
                  const float* __restrict__ gamma,
                  const float* __restrict__ beta,
                  float* __restrict__ out,
                  int nc, int nf,
                  uint32_t wk0, uint32_t wk1,
                  uint32_t dk0, uint32_t dk1) {
    constexpr int TB = BATCH / SPLIT;      // batches per thread
    const int tid = blockIdx.x * blockDim.x + threadIdx.x;
    const int f = tid / SPLIT;
    const int sub = tid % SPLIT;
    const int lane = threadIdx.x & 31;
    const int gbase = lane & ~(SPLIT - 1);
    const int b0 = sub * TB;
    const bool wactive = (SPLIT == 4) || (sub < 4);

    float kl = 0.0f;
    {
        // ================= phase 1: issue all loads =================
        const int4 e4 = __ldg(reinterpret_cast<const int4*>(ii) + f);
        const int e[4] = {e4.x, e4.y, e4.z, e4.w};

        float xv[4][TB];
#pragma unroll
        for (int j = 0; j < 4; j++) {
            if (X_BATCH_MAJOR) {
#pragma unroll
                for (int t = 0; t < TB; t++)
                    xv[j][t] = __ldg(x + (size_t)(b0 + t) * nc + e[j]);
            } else if (TB == 4) {
                float4 v = __ldg(reinterpret_cast<const float4*>(x + (size_t)e[j] * BATCH) + sub);
                xv[j][0] = v.x; xv[j][1] = v.y; xv[j][2] = v.z; xv[j][3] = v.w;
            } else {  // TB == 2
                float2 v = __ldg(reinterpret_cast<const float2*>(x + (size_t)e[j] * BATCH) + sub);
                xv[j][0] = v.x; xv[j][1] = v.y;
            }
        }

        float mld[C], rld[C];
        if (wactive) {
#pragma unroll
            for (int o = 0; o < C; o++) {
                uint32_t idx = (uint32_t)((4 * f + sub) * C + o);
                mld[o] = __ldg(mu + idx);
                rld[o] = __ldg(rho + idx);
            }
        }
        float gg = 0.0f, bb = 0.0f;
        if (HASBN) { gg = __ldg(gamma + f); bb = __ldg(beta + f); }

        // ============ phase 2: all RNG chains (pure ALU, hides latency) ============
        uint32_t wb[C];
        if (wactive) {
#pragma unroll
            for (int o = 0; o < C; o++)
                wb[o] = rbits(wk0, wk1, (uint32_t)((4 * f + sub) * C + o));
        }
        uint32_t db[HASBN ? TB : 1];
        if (HASBN) {
#pragma unroll
            for (int t = 0; t < TB; t++)
                db[t] = rbits(dk0, dk1, (uint32_t)((b0 + t) * nf + f));
        }

        // ============ phase 3: transforms ============
        float w_own[C];
#pragma unroll
        for (int o = 0; o < C; o++) w_own[o] = 0.0f;
        if (wactive) {
#pragma unroll
            for (int o = 0; o < C; o++) {
                float eps = bits_to_normal(wb[o]);
                float m = mld[o], r = rld[o];
                float t = __expf(-fabsf(r));
                float sp = fmaxf(r, 0.0f) + __logf(1.0f + t);   // softplus
                w_own[o] = fmaf(sp, eps, m);
                kl += 0.5f * (sp * sp + m * m) - __logf(sp) - 0.5f;
            }
        }

        float w[4][C];
#pragma unroll
        for (int j = 0; j < 4; j++)
#pragma unroll
            for (int o = 0; o < C; o++)
                w[j][o] = __shfl_sync(0xffffffffu, w_own[o], gbase + j);

        // ============ phase 4: FMA accumulate ============
        float acc[TB][C];
#pragma unroll
        for (int t = 0; t < TB; t++)
#pragma unroll
            for (int o = 0; o < C; o++) acc[t][o] = 0.0f;
#pragma unroll
        for (int j = 0; j < 4; j++)
#pragma unroll
            for (int t = 0; t < TB; t++)
#pragma unroll
                for (int o = 0; o < C; o++)
                    acc[t][o] = fmaf(xv[j][t], w[j][o], acc[t][o]);

        // ============ phase 5: BN + ReLU + dropout / store ============
        if (HASBN) {  // C == 1 on BN stages
            float s = 0.0f;
#pragma unroll
            for (int t = 0; t < TB; t++) s += acc[t][0];
#pragma unroll
            for (int off = 1; off < SPLIT; off <<= 1)
                s += __shfl_xor_sync(0xffffffffu, s, off);
            float m = s * (1.0f / BATCH);
            float d2 = 0.0f;
#pragma unroll
            for (int t = 0; t < TB; t++) { float d = acc[t][0] - m; d2 = fmaf(d, d, d2); }
#pragma unroll
            for (int off = 1; off < SPLIT; off <<= 1)
                d2 += __shfl_xor_sync(0xffffffffu, d2, off);
            float inv = rsqrtf(d2 * (1.0f / BATCH) + 1e-5f);
            float vals[TB];
#pragma unroll
            for (int t = 0; t < TB; t++) {
                float v = fmaxf((acc[t][0] - m) * inv * gg + bb, 0.0f);
                vals[t] = (db[t] < DROP_KEEP_THRESH) ? v * INV_KEEP : 0.0f;
            }
            if (TB == 4) {
                reinterpret_cast<float4*>(out + (size_t)f * BATCH)[sub] =
                    make_float4(vals[0], vals[1], vals[2], vals[3]);
            } else {
                reinterpret_cast<float2*>(out + (size_t)f * BATCH)[sub] =
                    make_float2(vals[0], vals[1]);
            }
        } else {  // final stage: out layout [B, nf, C]
#pragma unroll
            for (int t = 0; t < TB; t++) {
                size_t base = (size_t)(b0 + t) * nf * C + (size_t)f * C;
#pragma unroll
                for (int o = 0; o < C; o++) out[base + o] = acc[t][o];
            }
        }
    }

    // KL block reduction -> double atomic
#pragma unroll
    for (int off = 16; off > 0; off >>= 1)
        kl += __shfl_down_sync(0xffffffffu, kl, off);
    __shared__ float wsum[8];
    int wid = threadIdx.x >> 5;
    if (lane == 0) wsum[wid] = kl;
    __syncthreads();
    if (threadIdx.x == 0) {
        double s = 0.0;
        int nw = (blockDim.x + 31) >> 5;
        for (int i = 0; i < nw; i++) s += (double)wsum[i];
        atomicAdd(&g_kl, s);
    }
}

__global__ void zero_kl_kernel() { g_kl = 0.0; }
__global__ void write_kl_kernel(float* out, size_t idx) { out[idx] = (float)g_kl; }

// ---------------- launch ----------------
extern "C" void kernel_launch(void* const* d_in, const int* in_sizes, int n_in,
                              void* d_out, int out_size) {
    (void)in_sizes; (void)n_in;
    const float* x = (const float*)d_in[0];
    const int*   ii[5]  = {(const int*)d_in[2],  (const int*)d_in[8],  (const int*)d_in[14],
                           (const int*)d_in[20], (const int*)d_in[26]};
    const float* mu[5]  = {(const float*)d_in[3],  (const float*)d_in[9],  (const float*)d_in[15],
                           (const float*)d_in[21], (const float*)d_in[27]};
    const float* rho[5] = {(const float*)d_in[4],  (const float*)d_in[10], (const float*)d_in[16],
                           (const float*)d_in[22], (const float*)d_in[28]};
    const float* gam[4] = {(const float*)d_in[5],  (const float*)d_in[11],
                           (const float*)d_in[17], (const float*)d_in[23]};
    const float* bet[4] = {(const float*)d_in[6],  (const float*)d_in[12],
                           (const float*)d_in[18], (const float*)d_in[24]};

    // keys = split(key(42), 10), partitionable fold-like: keys[m] = tf((0,42), 0, m)
    uint32_t k[10][2];
    for (uint32_t m = 0; m < 10; m++) tf2x32(0u, 42u, 0u, m, k[m][0], k[m][1]);

    float *h1, *h2, *h3, *h4;
    cudaGetSymbolAddress((void**)&h1, g_h1);
    cudaGetSymbolAddress((void**)&h2, g_h2);
    cudaGetSymbolAddress((void**)&h3, g_h3);
    cudaGetSymbolAddress((void**)&h4, g_h4);

    zero_kl_kernel<<<1, 1>>>();

    // grid = nf*SPLIT threads / 256
    stage_kernel<1, 8, true, true><<<2048 * 8 / 256, 256>>>(
        x, ii[0], mu[0], rho[0], gam[0], bet[0], h1, 512, 2048,
        k[0][0], k[0][1], k[1][0], k[1][1]);
    stage_kernel<1, 8, true, false><<<8192 * 8 / 256, 256>>>(
        h1, ii[1], mu[1], rho[1], gam[1], bet[1], h2, 2048, 8192,
        k[2][0], k[2][1], k[3][0], k[3][1]);
    stage_kernel<1, 8, true, false><<<32768 * 8 / 256, 256>>>(
        h2, ii[2], mu[2], rho[2], gam[2], bet[2], h3, 8192, 32768,
        k[4][0], k[4][1], k[5][0], k[5][1]);
    stage_kernel<1, 4, true, false><<<131072 * 4 / 256, 256>>>(
        h3, ii[3], mu[3], rho[3], gam[3], bet[3], h4, 32768, 131072,
        k[6][0], k[6][1], k[7][0], k[7][1]);
    stage_kernel<3, 4, false, false><<<524288 * 4 / 256, 256>>>(
        h4, ii[4], mu[4], rho[4], nullptr, nullptr, (float*)d_out, 131072, 524288,
        k[8][0], k[8][1], 0u, 0u);

    write_kl_kernel<<<1, 1>>>((float*)d_out, (size_t)out_size - 1);
}